// round 5
// baseline (speedup 1.0000x reference)
#include <cuda_runtime.h>

// Problem constants (B=2, S=2048, D=2048, K=8, R=8, F=D/4=512)
#define S_LEN 2048
#define D_MOD 2048
#define N_EXP 8
#define F_HID 512
#define N_TOK 4096   // B*S
#define KF    4096   // N_EXP*F_HID

// ---------------- device scratch (no allocations allowed) ----------------
__device__ float d_hid[N_TOK * KF];       // gelu(hL@W1+b1), token-indexed, only unmasked rows valid
__device__ float d_g[N_TOK * KF];         // compact masked rows: (w_k/cnt) * windowed hid
__device__ float d_mixed[N_TOK * D_MOD];  // compact masked rows: g @ W2_flat
__device__ float d_w[N_TOK * N_EXP];      // softmax routing weights
__device__ float d_ws[N_TOK * N_EXP];     // w / max(cnt,1)
__device__ unsigned char d_unm[N_TOK];    // 1 = unmasked
__device__ int d_cnt[N_TOK];
__device__ int d_mList[N_TOK];            // masked token ids (compact)
__device__ int d_uList[N_TOK];            // unmasked token ids (compact)
__device__ int d_mNum, d_uNum, d_r;

// ---------------- K0: counters, mask-dtype detection, r ----------------
__global__ void k_prep(const unsigned int* __restrict__ masked, const int* __restrict__ rPtr)
{
    __shared__ int not01, notf;
    const int tid = threadIdx.x;
    if (tid == 0) {
        not01 = 0; notf = 0;
        d_mNum = 0; d_uNum = 0;
        int rv = 8;
        if (rPtr) {
            rv = rPtr[0];
            if (rv < 0 || rv > 100000) {          // maybe it was stored as float
                float rf = __int_as_float(rv);
                rv = (rf > 0.0f && rf < 100000.0f) ? (int)rf : 8;
            }
            if (rv < 0) rv = 0;
            if (rv > S_LEN) rv = S_LEN;
        }
        d_r = rv;
    }
    __syncthreads();
    // Sniff first 4KB (safe for uint8 / int32 / float32 layouts of 4096 elems).
    int b01 = 0, bf = 0;
    for (int i = tid; i < N_TOK / 4; i += blockDim.x) {
        unsigned int v = masked[i];
        if (v > 1u) b01 = 1;
        if (v != 0u && v != 0x3F800000u) bf = 1;
    }
    if (b01) atomicOr(&not01, 1);
    if (bf)  atomicOr(&notf, 1);
    __syncthreads();
    const int mode = (!not01) ? 1 : ((!notf) ? 2 : 0); // 1=int32, 2=float32, 0=byte
    for (int t = tid; t < N_TOK; t += blockDim.x) {
        int mk;
        if (mode == 1)      mk = ((const int*)masked)[t];
        else if (mode == 2) mk = (((const float*)masked)[t] != 0.0f);
        else                mk = ((const unsigned char*)masked)[t];
        d_unm[t] = (unsigned char)(mk ? 0 : 1);
    }
}

// ---------------- K1: routing softmax + cnt + compaction ----------------
__global__ __launch_bounds__(256) void k_route(const float* __restrict__ hL,
                                               const float* __restrict__ Wr,
                                               const float* __restrict__ br)
{
    const int t = blockIdx.x;
    const int tid = threadIdx.x;
    const float* __restrict__ h = hL + (size_t)t * D_MOD;

    float acc[8];
#pragma unroll
    for (int k = 0; k < 8; k++) acc[k] = 0.0f;

    for (int d = tid; d < D_MOD; d += 256) {
        float hv = h[d];
        const float4* wr = (const float4*)(Wr + (size_t)d * 8);
        float4 w0 = wr[0], w1 = wr[1];
        acc[0] = fmaf(hv, w0.x, acc[0]);
        acc[1] = fmaf(hv, w0.y, acc[1]);
        acc[2] = fmaf(hv, w0.z, acc[2]);
        acc[3] = fmaf(hv, w0.w, acc[3]);
        acc[4] = fmaf(hv, w1.x, acc[4]);
        acc[5] = fmaf(hv, w1.y, acc[5]);
        acc[6] = fmaf(hv, w1.z, acc[6]);
        acc[7] = fmaf(hv, w1.w, acc[7]);
    }
#pragma unroll
    for (int k = 0; k < 8; k++) {
#pragma unroll
        for (int o = 16; o; o >>= 1) acc[k] += __shfl_xor_sync(0xffffffffu, acc[k], o);
    }
    __shared__ float sl[8][8];
    if ((tid & 31) == 0) {
#pragma unroll
        for (int k = 0; k < 8; k++) sl[tid >> 5][k] = acc[k];
    }
    __syncthreads();
    if (tid == 0) {
        float lg[8];
#pragma unroll
        for (int k = 0; k < 8; k++) {
            float s = br[k];
            for (int wgi = 0; wgi < 8; wgi++) s += sl[wgi][k];
            lg[k] = s;
        }
        // windowed neighbor count (excluding self; self is 0 anyway if masked)
        const int b = t / S_LEN, s0 = t - b * S_LEN;
        const int r = d_r;
        int lo = s0 - r; if (lo < 0) lo = 0;
        int hi = s0 + r; if (hi > S_LEN - 1) hi = S_LEN - 1;
        int c = 0;
        for (int j = lo; j <= hi; j++)
            if (j != s0) c += (int)d_unm[b * S_LEN + j];
        d_cnt[t] = c;

        float mx = lg[0];
#pragma unroll
        for (int k = 1; k < 8; k++) mx = fmaxf(mx, lg[k]);
        float e[8], ssum = 0.0f;
#pragma unroll
        for (int k = 0; k < 8; k++) { e[k] = expf(lg[k] - mx); ssum += e[k]; }
        const float inv = 1.0f / ssum;
        const float cinv = 1.0f / (float)(c > 0 ? c : 1);
#pragma unroll
        for (int k = 0; k < 8; k++) {
            float wv = e[k] * inv;
            d_w[t * 8 + k] = wv;
            d_ws[t * 8 + k] = wv * cinv;
        }
        if (d_unm[t]) { int u = atomicAdd(&d_uNum, 1); d_uList[u] = t; }
        else          { int mm = atomicAdd(&d_mNum, 1); d_mList[mm] = t; }
    }
}

// ---------------- K2: GEMM1  hid = gelu(hL[unmasked] @ W1_e + b1_e) ----------------
// 128x128x8 SGEMM, 256 threads, 8x8 per-thread microtile; gridDim.z = expert.
__global__ __launch_bounds__(256, 2) void k_gemm1(const float* __restrict__ hL,
                                                  const float* __restrict__ W1,
                                                  const float* __restrict__ b1)
{
    const int M = d_uNum;
    const int m0 = blockIdx.y * 128;
    if (m0 >= M) return;
    const int n0 = blockIdx.x * 128;           // within F_HID=512
    const int e  = blockIdx.z;
    const float* __restrict__ Bm = W1 + (size_t)e * D_MOD * F_HID;

    __shared__ float As[8][128];
    __shared__ float Bs[8][128];
    __shared__ int rows[128];

    const int tid = threadIdx.x;
    for (int i = tid; i < 128; i += 256) {
        int m = m0 + i;
        rows[i] = d_uList[(m < M) ? m : 0];    // clamp: garbage rows never stored
    }
    __syncthreads();

    const int aRow = tid >> 1;
    const int aCol = (tid & 1) << 2;
    const int bRow = tid >> 5;
    const int bCol = (tid & 31) << 2;
    const int ty = tid >> 4, tx = tid & 15;
    const int mr = ty << 3, nr = tx << 3;

    const float* aPtr = hL + (size_t)rows[aRow] * D_MOD + aCol;
    const float* bPtr = Bm + (size_t)bRow * F_HID + n0 + bCol;

    float acc[8][8];
#pragma unroll
    for (int i = 0; i < 8; i++)
#pragma unroll
        for (int j = 0; j < 8; j++) acc[i][j] = 0.0f;

    for (int kb = 0; kb < D_MOD; kb += 8) {
        float4 av = *(const float4*)(aPtr + kb);
        float4 bv = *(const float4*)(bPtr + (size_t)kb * F_HID);
        As[aCol + 0][aRow] = av.x;
        As[aCol + 1][aRow] = av.y;
        As[aCol + 2][aRow] = av.z;
        As[aCol + 3][aRow] = av.w;
        *(float4*)&Bs[bRow][bCol] = bv;
        __syncthreads();
#pragma unroll
        for (int kk = 0; kk < 8; kk++) {
            float a[8], b[8];
            *(float4*)&a[0] = *(const float4*)&As[kk][mr];
            *(float4*)&a[4] = *(const float4*)&As[kk][mr + 4];
            *(float4*)&b[0] = *(const float4*)&Bs[kk][nr];
            *(float4*)&b[4] = *(const float4*)&Bs[kk][nr + 4];
#pragma unroll
            for (int i = 0; i < 8; i++)
#pragma unroll
                for (int j = 0; j < 8; j++)
                    acc[i][j] = fmaf(a[i], b[j], acc[i][j]);
        }
        __syncthreads();
    }

#pragma unroll
    for (int i = 0; i < 8; i++) {
        const int m = m0 + mr + i;
        if (m >= M) continue;
        const int t = rows[mr + i];
        float* outp = d_hid + (size_t)t * KF + e * F_HID + n0 + nr;
        const float* bb = b1 + e * F_HID + n0 + nr;
#pragma unroll
        for (int j = 0; j < 8; j++) {
            float x = acc[i][j] + bb[j];
            outp[j] = 0.5f * x * (1.0f + erff(x * 0.70710678118654752f)); // exact-erf GELU
        }
    }
}

// ---------------- K3: windowed gather + (w/cnt) scaling, compact masked rows ----------------
__global__ __launch_bounds__(512) void k_window()
{
    const int m = blockIdx.x;
    if (m >= d_mNum) return;
    const int t = d_mList[m];
    const int b = t / S_LEN, s = t - b * S_LEN;
    const int r = d_r;
    int lo = s - r; if (lo < 0) lo = 0;
    int hi = s + r; if (hi > S_LEN - 1) hi = S_LEN - 1;
    const int tid = threadIdx.x;   // 512 threads, 2x float4 per thread (KF=4096)

    float4 a0 = make_float4(0.f, 0.f, 0.f, 0.f);
    float4 a1 = make_float4(0.f, 0.f, 0.f, 0.f);
    for (int j = lo; j <= hi; j++) {
        if (!d_unm[b * S_LEN + j]) continue;   // masked neighbors (and self) contribute 0
        const float4* h = (const float4*)(d_hid + (size_t)(b * S_LEN + j) * KF);
        float4 v0 = h[tid], v1 = h[tid + 512];
        a0.x += v0.x; a0.y += v0.y; a0.z += v0.z; a0.w += v0.w;
        a1.x += v1.x; a1.y += v1.y; a1.z += v1.z; a1.w += v1.w;
    }
    const float s0 = d_ws[t * N_EXP + (tid >> 7)];       // expert of float4 idx tid
    const float s1 = d_ws[t * N_EXP + (tid >> 7) + 4];   // expert of float4 idx tid+512
    a0.x *= s0; a0.y *= s0; a0.z *= s0; a0.w *= s0;
    a1.x *= s1; a1.y *= s1; a1.z *= s1; a1.w *= s1;
    float4* g = (float4*)(d_g + (size_t)m * KF);
    g[tid] = a0;
    g[tid + 512] = a1;
}

// ---------------- K4: GEMM2  mixed = g[masked,4096] @ W2_flat[4096,2048] ----------------
__global__ __launch_bounds__(256, 2) void k_gemm2(const float* __restrict__ W2)
{
    const int M = d_mNum;
    const int m0 = blockIdx.y * 128;
    if (m0 >= M) return;
    const int n0 = blockIdx.x * 128;

    __shared__ float As[8][128];
    __shared__ float Bs[8][128];

    const int tid = threadIdx.x;
    const int aRow = tid >> 1;
    const int aCol = (tid & 1) << 2;
    const int bRow = tid >> 5;
    const int bCol = (tid & 31) << 2;
    const int ty = tid >> 4, tx = tid & 15;
    const int mr = ty << 3, nr = tx << 3;

    const float* aPtr = d_g + (size_t)(m0 + aRow) * KF + aCol;  // stays in-bounds of scratch
    const float* bPtr = W2 + (size_t)bRow * D_MOD + n0 + bCol;

    float acc[8][8];
#pragma unroll
    for (int i = 0; i < 8; i++)
#pragma unroll
        for (int j = 0; j < 8; j++) acc[i][j] = 0.0f;

    for (int kb = 0; kb < KF; kb += 8) {
        float4 av = *(const float4*)(aPtr + kb);
        float4 bv = *(const float4*)(bPtr + (size_t)kb * D_MOD);
        As[aCol + 0][aRow] = av.x;
        As[aCol + 1][aRow] = av.y;
        As[aCol + 2][aRow] = av.z;
        As[aCol + 3][aRow] = av.w;
        *(float4*)&Bs[bRow][bCol] = bv;
        __syncthreads();
#pragma unroll
        for (int kk = 0; kk < 8; kk++) {
            float a[8], b[8];
            *(float4*)&a[0] = *(const float4*)&As[kk][mr];
            *(float4*)&a[4] = *(const float4*)&As[kk][mr + 4];
            *(float4*)&b[0] = *(const float4*)&Bs[kk][nr];
            *(float4*)&b[4] = *(const float4*)&Bs[kk][nr + 4];
#pragma unroll
            for (int i = 0; i < 8; i++)
#pragma unroll
                for (int j = 0; j < 8; j++)
                    acc[i][j] = fmaf(a[i], b[j], acc[i][j]);
        }
        __syncthreads();
    }

#pragma unroll
    for (int i = 0; i < 8; i++) {
        const int m = m0 + mr + i;
        if (m >= M) continue;
        float* o = d_mixed + (size_t)m * D_MOD + n0 + nr;
#pragma unroll
        for (int j = 0; j < 8; j++) o[j] = acc[i][j];
    }
}

// ---------------- K5: bias (Σ w_k b2_k) + LayerNorm + scatter ----------------
__global__ __launch_bounds__(256) void k_final(const float* __restrict__ b2,
                                               float* __restrict__ out)
{
    const int m = blockIdx.x;
    if (m >= d_mNum) return;
    const int t = d_mList[m];
    if (d_cnt[t] <= 0) return;   // invalid: output stays zero
    const int tid = threadIdx.x;

    float w[8];
#pragma unroll
    for (int k = 0; k < 8; k++) w[k] = d_w[t * 8 + k];

    float x[8];
    float sum = 0.0f;
#pragma unroll
    for (int i = 0; i < 8; i++) {
        const int d = tid + (i << 8);
        float v = d_mixed[(size_t)m * D_MOD + d];
        float bias = 0.0f;
#pragma unroll
        for (int k = 0; k < 8; k++) bias = fmaf(w[k], b2[k * D_MOD + d], bias);
        v += bias;
        x[i] = v;
        sum += v;
    }
    __shared__ float sh[8];
#pragma unroll
    for (int o = 16; o; o >>= 1) sum += __shfl_xor_sync(0xffffffffu, sum, o);
    if ((tid & 31) == 0) sh[tid >> 5] = sum;
    __syncthreads();
    const float mu = (sh[0] + sh[1] + sh[2] + sh[3] + sh[4] + sh[5] + sh[6] + sh[7]) *
                     (1.0f / (float)D_MOD);
    __syncthreads();
    float vs = 0.0f;
#pragma unroll
    for (int i = 0; i < 8; i++) { float dd = x[i] - mu; vs = fmaf(dd, dd, vs); }
#pragma unroll
    for (int o = 16; o; o >>= 1) vs += __shfl_xor_sync(0xffffffffu, vs, o);
    if ((tid & 31) == 0) sh[tid >> 5] = vs;
    __syncthreads();
    const float var = (sh[0] + sh[1] + sh[2] + sh[3] + sh[4] + sh[5] + sh[6] + sh[7]) *
                      (1.0f / (float)D_MOD);
    const float rstd = rsqrtf(var + 1e-5f);
    float* op = out + (size_t)t * D_MOD;
#pragma unroll
    for (int i = 0; i < 8; i++) op[tid + (i << 8)] = (x[i] - mu) * rstd;
}

// ---------------- launch ----------------
extern "C" void kernel_launch(void* const* d_in, const int* in_sizes, int n_in,
                              void* d_out, int out_size)
{
    const float* hL = (const float*)d_in[0];
    const void*  mk = d_in[1];
    const float* Wr = (const float*)d_in[2];
    const float* br = (const float*)d_in[3];
    const float* W1 = (const float*)d_in[4];
    const float* b1 = (const float*)d_in[5];
    const float* W2 = (const float*)d_in[6];
    const float* b2 = (const float*)d_in[7];
    const int*   rp = (n_in > 8) ? (const int*)d_in[8] : nullptr;
    float* out = (float*)d_out;

    cudaMemsetAsync(out, 0, (size_t)out_size * sizeof(float));

    k_prep<<<1, 256>>>((const unsigned int*)mk, rp);
    k_route<<<N_TOK, 256>>>(hL, Wr, br);
    k_gemm1<<<dim3(4, 32, 8), 256>>>(hL, W1, b1);   // worst-case grid; blocks self-guard on d_uNum
    k_window<<<N_TOK, 512>>>();                     // worst-case grid; guards on d_mNum
    k_gemm2<<<dim3(16, 32, 1), 256>>>(W2);          // worst-case grid; guards on d_mNum
    k_final<<<N_TOK, 256>>>(b2, out);
    (void)in_sizes;
}

// round 8
// speedup vs baseline: 5.1373x; 5.1373x over previous
#include <cuda_runtime.h>
#include <cuda_fp16.h>

// Problem constants (B=2, S=2048, D=2048, K=8, R=8, F=512)
#define S_LEN 2048
#define D_MOD 2048
#define N_EXP 8
#define F_HID 512
#define N_TOK 4096   // B*S
#define KF    4096   // N_EXP*F_HID

// ---------------- device scratch (no allocations allowed) ----------------
__device__ __half d_A1h[(size_t)N_TOK * D_MOD];   // gathered unmasked hL rows, fp16
__device__ __half d_B1h[(size_t)KF * D_MOD];      // W1 transposed: row n=e*512+f, col k
__device__ __half d_A2h[(size_t)N_TOK * KF];      // windowed+scaled hidden, compact masked
__device__ __half d_B2h[(size_t)D_MOD * KF];      // W2 transposed: row n, col k
__device__ float d_hid[(size_t)N_TOK * KF];       // gelu(hL@W1+b1), token-indexed
__device__ float d_mixed[(size_t)N_TOK * D_MOD];  // compact masked rows
__device__ float d_w[N_TOK * N_EXP];
__device__ float d_ws[N_TOK * N_EXP];
__device__ unsigned char d_unm[N_TOK];
__device__ int d_cnt[N_TOK];
__device__ int d_mList[N_TOK];
__device__ int d_uList[N_TOK];
__device__ int d_mNum, d_uNum, d_r;

// ---------------- PTX helpers ----------------
__device__ __forceinline__ unsigned s2u(const void* p) {
    unsigned a;
    asm("{ .reg .u64 t; cvta.to.shared.u64 t, %1; cvt.u32.u64 %0, t; }" : "=r"(a) : "l"(p));
    return a;
}
__device__ __forceinline__ void cp16(unsigned d, const void* s) {
    asm volatile("cp.async.cg.shared.global [%0], [%1], 16;\n" :: "r"(d), "l"(s));
}
#define CP_COMMIT() asm volatile("cp.async.commit_group;\n")
#define CP_WAIT1()  asm volatile("cp.async.wait_group 1;\n" ::: "memory")
#define CP_WAIT0()  asm volatile("cp.async.wait_group 0;\n" ::: "memory")

#define LDSM4(r0, r1, r2, r3, addr) \
    asm volatile("ldmatrix.sync.aligned.m8n8.x4.shared.b16 {%0,%1,%2,%3}, [%4];" \
                 : "=r"(r0), "=r"(r1), "=r"(r2), "=r"(r3) : "r"(addr))

#define MMA16816(c0, c1, c2, c3, a0, a1, a2, a3, b0, b1) \
    asm volatile("mma.sync.aligned.m16n8k16.row.col.f32.f16.f16.f32 " \
                 "{%0,%1,%2,%3}, {%4,%5,%6,%7}, {%8,%9}, {%0,%1,%2,%3};" \
                 : "+f"(c0), "+f"(c1), "+f"(c2), "+f"(c3) \
                 : "r"(a0), "r"(a1), "r"(a2), "r"(a3), "r"(b0), "r"(b1))

// ---------------- K0: counters, mask-dtype detection, r ----------------
__global__ void k_prep(const unsigned int* __restrict__ masked, const int* __restrict__ rPtr)
{
    __shared__ int not01, notf;
    const int tid = threadIdx.x;
    if (tid == 0) {
        not01 = 0; notf = 0;
        d_mNum = 0; d_uNum = 0;
        int rv = 8;
        if (rPtr) {
            rv = rPtr[0];
            if (rv < 0 || rv > 100000) {
                float rf = __int_as_float(rv);
                rv = (rf > 0.0f && rf < 100000.0f) ? (int)rf : 8;
            }
            if (rv < 0) rv = 0;
            if (rv > S_LEN) rv = S_LEN;
        }
        d_r = rv;
    }
    __syncthreads();
    int b01 = 0, bf = 0;
    for (int i = tid; i < N_TOK / 4; i += blockDim.x) {
        unsigned int v = masked[i];
        if (v > 1u) b01 = 1;
        if (v != 0u && v != 0x3F800000u) bf = 1;
    }
    if (b01) atomicOr(&not01, 1);
    if (bf)  atomicOr(&notf, 1);
    __syncthreads();
    const int mode = (!not01) ? 1 : ((!notf) ? 2 : 0);
    for (int t = tid; t < N_TOK; t += blockDim.x) {
        int mk;
        if (mode == 1)      mk = ((const int*)masked)[t];
        else if (mode == 2) mk = (((const float*)masked)[t] != 0.0f);
        else                mk = ((const unsigned char*)masked)[t];
        d_unm[t] = (unsigned char)(mk ? 0 : 1);
    }
}

// ---------------- K1: routing softmax + cnt + compaction ----------------
__global__ __launch_bounds__(256) void k_route(const float* __restrict__ hL,
                                               const float* __restrict__ Wr,
                                               const float* __restrict__ br)
{
    const int t = blockIdx.x;
    const int tid = threadIdx.x;
    const float* __restrict__ h = hL + (size_t)t * D_MOD;

    float acc[8];
#pragma unroll
    for (int k = 0; k < 8; k++) acc[k] = 0.0f;
    for (int d = tid; d < D_MOD; d += 256) {
        float hv = h[d];
        const float4* wr = (const float4*)(Wr + (size_t)d * 8);
        float4 w0 = wr[0], w1 = wr[1];
        acc[0] = fmaf(hv, w0.x, acc[0]); acc[1] = fmaf(hv, w0.y, acc[1]);
        acc[2] = fmaf(hv, w0.z, acc[2]); acc[3] = fmaf(hv, w0.w, acc[3]);
        acc[4] = fmaf(hv, w1.x, acc[4]); acc[5] = fmaf(hv, w1.y, acc[5]);
        acc[6] = fmaf(hv, w1.z, acc[6]); acc[7] = fmaf(hv, w1.w, acc[7]);
    }
#pragma unroll
    for (int k = 0; k < 8; k++) {
#pragma unroll
        for (int o = 16; o; o >>= 1) acc[k] += __shfl_xor_sync(0xffffffffu, acc[k], o);
    }
    __shared__ float sl[8][8];
    if ((tid & 31) == 0) {
#pragma unroll
        for (int k = 0; k < 8; k++) sl[tid >> 5][k] = acc[k];
    }
    __syncthreads();
    if (tid == 0) {
        float lg[8];
#pragma unroll
        for (int k = 0; k < 8; k++) {
            float s = br[k];
            for (int wgi = 0; wgi < 8; wgi++) s += sl[wgi][k];
            lg[k] = s;
        }
        const int b = t / S_LEN, s0 = t - b * S_LEN;
        const int r = d_r;
        int lo = s0 - r; if (lo < 0) lo = 0;
        int hi = s0 + r; if (hi > S_LEN - 1) hi = S_LEN - 1;
        int c = 0;
        for (int j = lo; j <= hi; j++)
            if (j != s0) c += (int)d_unm[b * S_LEN + j];
        d_cnt[t] = c;

        float mx = lg[0];
#pragma unroll
        for (int k = 1; k < 8; k++) mx = fmaxf(mx, lg[k]);
        float e[8], ssum = 0.0f;
#pragma unroll
        for (int k = 0; k < 8; k++) { e[k] = expf(lg[k] - mx); ssum += e[k]; }
        const float inv = 1.0f / ssum;
        const float cinv = 1.0f / (float)(c > 0 ? c : 1);
#pragma unroll
        for (int k = 0; k < 8; k++) {
            float wv = e[k] * inv;
            d_w[t * 8 + k] = wv;
            d_ws[t * 8 + k] = wv * cinv;
        }
        if (d_unm[t]) { int u = atomicAdd(&d_uNum, 1); d_uList[u] = t; }
        else          { int mm = atomicAdd(&d_mNum, 1); d_mList[mm] = t; }
    }
}

// ---------------- K2: gather unmasked hL rows -> fp16 (A1) ----------------
__global__ __launch_bounds__(256) void k_cvtA1(const float* __restrict__ hL)
{
    const int m = blockIdx.x;
    if (m >= d_uNum) return;
    const int t = d_uList[m];
    const float4* src = (const float4*)(hL + (size_t)t * D_MOD);
    __half* dst = d_A1h + (size_t)m * D_MOD;
    for (int i = threadIdx.x; i < D_MOD / 4; i += 256) {
        float4 v = src[i];
        __half2 p0 = __floats2half2_rn(v.x, v.y);
        __half2 p1 = __floats2half2_rn(v.z, v.w);
        *(uint2*)(dst + i * 4) = make_uint2(*(unsigned*)&p0, *(unsigned*)&p1);
    }
}

// ---------------- transpose + fp16 convert: W[K,N] -> B[N,K] ----------------
__device__ __forceinline__ void tr_body(const float* __restrict__ Wp,
                                        __half* __restrict__ Bp, int Kd, int Nd)
{
    __shared__ float tl[32][33];
    const int tx = threadIdx.x & 31, ty = threadIdx.x >> 5;
    const int n0 = blockIdx.x * 32, k0 = blockIdx.y * 32;
#pragma unroll
    for (int j = 0; j < 4; j++) {
        int r = ty + j * 8;
        tl[r][tx] = Wp[(size_t)(k0 + r) * Nd + n0 + tx];
    }
    __syncthreads();
#pragma unroll
    for (int j = 0; j < 4; j++) {
        int r = ty + j * 8;
        Bp[(size_t)(n0 + r) * Kd + k0 + tx] = __float2half_rn(tl[tx][r]);
    }
}
__global__ __launch_bounds__(256) void k_tr1(const float* __restrict__ W1) {
    tr_body(W1 + (size_t)blockIdx.z * D_MOD * F_HID,
            d_B1h + (size_t)blockIdx.z * F_HID * D_MOD, D_MOD, F_HID);
}
__global__ __launch_bounds__(256) void k_tr2(const float* __restrict__ W2) {
    tr_body(W2, d_B2h, KF, D_MOD);
}

// ---------------- HMMA GEMM: 128x128 CTA tile, 8 warps, cp.async double buffer ----
// MODE 0: hid[uList[m]][n] = gelu(A1[m] . B1[n] + b1[n]),  M=uNum, N=4096, K=2048
// MODE 1: mixed[m][n]      = A2[m] . B2[n],                M=mNum, N=2048, K=4096
template <int MODE>
__global__ __launch_bounds__(256, 2) void k_mm(const float* __restrict__ bias)
{
    constexpr int KDIM = (MODE == 0) ? D_MOD : KF;
    constexpr int KT = KDIM / 32;
    const __half* __restrict__ A  = (MODE == 0) ? d_A1h : d_A2h;
    const __half* __restrict__ Bm = (MODE == 0) ? d_B1h : d_B2h;
    const int M = (MODE == 0) ? d_uNum : d_mNum;
    const int m0 = blockIdx.y * 128;
    if (m0 >= M) return;
    const int n0 = blockIdx.x * 128;

    // padded stride 40 halves (80B): conflict-free ldmatrix, 16B-aligned segments
    __shared__ __align__(16) __half sA[2][128 * 40];
    __shared__ __align__(16) __half sB[2][128 * 40];

    const int tid = threadIdx.x;
    const int wid = tid >> 5, l = tid & 31;
    const unsigned baseA = s2u(&sA[0][0]);
    const unsigned baseB = s2u(&sB[0][0]);

    auto load_tile = [&](int buf, int kt) {
#pragma unroll
        for (int h = 0; h < 2; h++) {
            const int c = tid + h * 256;          // 512 16B chunks per tile
            const int r = c >> 2, sg = c & 3;
            const unsigned off = (unsigned)(buf * 5120 + r * 40 + sg * 8) * 2u;
            cp16(baseA + off, A + (size_t)(m0 + r) * KDIM + kt * 32 + sg * 8);
            cp16(baseB + off, Bm + (size_t)(n0 + r) * KDIM + kt * 32 + sg * 8);
        }
        CP_COMMIT();
    };

    load_tile(0, 0);
    load_tile(1, 1);

    float acc[4][4][4];
#pragma unroll
    for (int i = 0; i < 4; i++)
#pragma unroll
        for (int j = 0; j < 4; j++)
#pragma unroll
            for (int q = 0; q < 4; q++) acc[i][j][q] = 0.0f;

    const int wm = (wid >> 2) * 64, wn = (wid & 3) * 32;
    const int aRow = l & 15;
    const int aCol = (l >> 4) * 8;
    const int bRow = (l & 7) + ((l >> 4) & 1) * 8;
    const int bCol = ((l >> 3) & 1) * 8;

    for (int kt = 0; kt < KT; kt++) {
        if (kt < KT - 1) { CP_WAIT1(); } else { CP_WAIT0(); }
        __syncthreads();
        const int buf = kt & 1;
        const unsigned abuf = baseA + buf * 10240u;
        const unsigned bbuf = baseB + buf * 10240u;
#pragma unroll
        for (int ks = 0; ks < 2; ks++) {
            const int k0 = ks * 16;
            unsigned ar[4][4], br[2][4];
#pragma unroll
            for (int mi = 0; mi < 4; mi++) {
                unsigned ad = abuf + (unsigned)((wm + mi * 16 + aRow) * 40 + k0 + aCol) * 2u;
                LDSM4(ar[mi][0], ar[mi][1], ar[mi][2], ar[mi][3], ad);
            }
#pragma unroll
            for (int nj = 0; nj < 2; nj++) {
                unsigned bd = bbuf + (unsigned)((wn + nj * 16 + bRow) * 40 + k0 + bCol) * 2u;
                LDSM4(br[nj][0], br[nj][1], br[nj][2], br[nj][3], bd);
            }
#pragma unroll
            for (int mi = 0; mi < 4; mi++)
#pragma unroll
                for (int ni = 0; ni < 4; ni++)
                    MMA16816(acc[mi][ni][0], acc[mi][ni][1], acc[mi][ni][2], acc[mi][ni][3],
                             ar[mi][0], ar[mi][1], ar[mi][2], ar[mi][3],
                             br[ni >> 1][(ni & 1) * 2], br[ni >> 1][(ni & 1) * 2 + 1]);
        }
        __syncthreads();
        if (kt + 2 < KT) load_tile(buf, kt + 2);
    }

    // ---- epilogue ----
#pragma unroll
    for (int mi = 0; mi < 4; mi++) {
#pragma unroll
        for (int hh = 0; hh < 2; hh++) {
            const int m = m0 + wm + mi * 16 + (l >> 2) + hh * 8;
            if (m >= M) continue;
            int t = 0;
            if (MODE == 0) t = d_uList[m];
#pragma unroll
            for (int ni = 0; ni < 4; ni++) {
                const int n = n0 + wn + ni * 8 + (l & 3) * 2;
                float v0 = acc[mi][ni][hh * 2 + 0];
                float v1 = acc[mi][ni][hh * 2 + 1];
                if (MODE == 0) {
                    float x0 = v0 + bias[n];
                    float x1 = v1 + bias[n + 1];
                    float2 o;
                    o.x = 0.5f * x0 * (1.0f + erff(x0 * 0.70710678118654752f));
                    o.y = 0.5f * x1 * (1.0f + erff(x1 * 0.70710678118654752f));
                    *(float2*)(d_hid + (size_t)t * KF + n) = o;
                } else {
                    *(float2*)(d_mixed + (size_t)m * D_MOD + n) = make_float2(v0, v1);
                }
            }
        }
    }
}

// ---------------- K3: windowed gather + (w/cnt) scaling -> fp16 (A2, compact) ----
__global__ __launch_bounds__(512) void k_window()
{
    const int m = blockIdx.x;
    if (m >= d_mNum) return;
    const int t = d_mList[m];
    const int b = t / S_LEN, s = t - b * S_LEN;
    const int r = d_r;
    int lo = s - r; if (lo < 0) lo = 0;
    int hi = s + r; if (hi > S_LEN - 1) hi = S_LEN - 1;
    const int tid = threadIdx.x;

    float4 a0 = make_float4(0.f, 0.f, 0.f, 0.f);
    float4 a1 = make_float4(0.f, 0.f, 0.f, 0.f);
    for (int j = lo; j <= hi; j++) {
        if (!d_unm[b * S_LEN + j]) continue;
        const float4* h = (const float4*)(d_hid + (size_t)(b * S_LEN + j) * KF);
        float4 v0 = h[tid], v1 = h[tid + 512];
        a0.x += v0.x; a0.y += v0.y; a0.z += v0.z; a0.w += v0.w;
        a1.x += v1.x; a1.y += v1.y; a1.z += v1.z; a1.w += v1.w;
    }
    const float s0 = d_ws[t * N_EXP + (tid >> 7)];
    const float s1 = d_ws[t * N_EXP + (tid >> 7) + 4];

    __half* row = d_A2h + (size_t)m * KF;
    __half2 p0 = __floats2half2_rn(a0.x * s0, a0.y * s0);
    __half2 p1 = __floats2half2_rn(a0.z * s0, a0.w * s0);
    *(uint2*)(row + tid * 4) = make_uint2(*(unsigned*)&p0, *(unsigned*)&p1);
    __half2 q0 = __floats2half2_rn(a1.x * s1, a1.y * s1);
    __half2 q1 = __floats2half2_rn(a1.z * s1, a1.w * s1);
    *(uint2*)(row + 2048 + tid * 4) = make_uint2(*(unsigned*)&q0, *(unsigned*)&q1);
}

// ---------------- K5: bias (Σ w_k b2_k) + LayerNorm + scatter ----------------
__global__ __launch_bounds__(256) void k_final(const float* __restrict__ b2,
                                               float* __restrict__ out)
{
    const int m = blockIdx.x;
    if (m >= d_mNum) return;
    const int t = d_mList[m];
    if (d_cnt[t] <= 0) return;
    const int tid = threadIdx.x;

    float w[8];
#pragma unroll
    for (int k = 0; k < 8; k++) w[k] = d_w[t * 8 + k];

    float x[8];
    float sum = 0.0f;
#pragma unroll
    for (int i = 0; i < 8; i++) {
        const int d = tid + (i << 8);
        float v = d_mixed[(size_t)m * D_MOD + d];
        float bias = 0.0f;
#pragma unroll
        for (int k = 0; k < 8; k++) bias = fmaf(w[k], b2[k * D_MOD + d], bias);
        v += bias;
        x[i] = v;
        sum += v;
    }
    __shared__ float sh[8];
#pragma unroll
    for (int o = 16; o; o >>= 1) sum += __shfl_xor_sync(0xffffffffu, sum, o);
    if ((tid & 31) == 0) sh[tid >> 5] = sum;
    __syncthreads();
    const float mu = (sh[0] + sh[1] + sh[2] + sh[3] + sh[4] + sh[5] + sh[6] + sh[7]) *
                     (1.0f / (float)D_MOD);
    __syncthreads();
    float vs = 0.0f;
#pragma unroll
    for (int i = 0; i < 8; i++) { float dd = x[i] - mu; vs = fmaf(dd, dd, vs); }
#pragma unroll
    for (int o = 16; o; o >>= 1) vs += __shfl_xor_sync(0xffffffffu, vs, o);
    if ((tid & 31) == 0) sh[tid >> 5] = vs;
    __syncthreads();
    const float var = (sh[0] + sh[1] + sh[2] + sh[3] + sh[4] + sh[5] + sh[6] + sh[7]) *
                      (1.0f / (float)D_MOD);
    const float rstd = rsqrtf(var + 1e-5f);
    float* op = out + (size_t)t * D_MOD;
#pragma unroll
    for (int i = 0; i < 8; i++) op[tid + (i << 8)] = (x[i] - mu) * rstd;
}

// ---------------- launch ----------------
extern "C" void kernel_launch(void* const* d_in, const int* in_sizes, int n_in,
                              void* d_out, int out_size)
{
    const float* hL = (const float*)d_in[0];
    const void*  mk = d_in[1];
    const float* Wr = (const float*)d_in[2];
    const float* br = (const float*)d_in[3];
    const float* W1 = (const float*)d_in[4];
    const float* b1 = (const float*)d_in[5];
    const float* W2 = (const float*)d_in[6];
    const float* b2 = (const float*)d_in[7];
    const int*   rp = (n_in > 8) ? (const int*)d_in[8] : nullptr;
    float* out = (float*)d_out;

    cudaMemsetAsync(out, 0, (size_t)out_size * sizeof(float));

    k_prep<<<1, 256>>>((const unsigned int*)mk, rp);
    k_route<<<N_TOK, 256>>>(hL, Wr, br);
    k_cvtA1<<<N_TOK, 256>>>(hL);                      // guards on d_uNum
    k_tr1<<<dim3(F_HID / 32, D_MOD / 32, N_EXP), 256>>>(W1);
    k_mm<0><<<dim3(32, 32), 256>>>(b1);               // worst-case grid; guards on d_uNum
    k_window<<<N_TOK, 512>>>();                       // guards on d_mNum
    k_tr2<<<dim3(D_MOD / 32, KF / 32), 256>>>(W2);
    k_mm<1><<<dim3(16, 32), 256>>>(nullptr);          // worst-case grid; guards on d_mNum
    k_final<<<N_TOK, 256>>>(b2, out);
    (void)in_sizes;
}

// round 9
// speedup vs baseline: 5.1668x; 1.0057x over previous
#include <cuda_runtime.h>
#include <cuda_fp16.h>

// Problem constants (B=2, S=2048, D=2048, K=8, R=8, F=512)
#define S_LEN 2048
#define D_MOD 2048
#define N_EXP 8
#define F_HID 512
#define N_TOK 4096   // B*S
#define KF    4096   // N_EXP*F_HID

// ---------------- device scratch (no allocations allowed) ----------------
__device__ __half d_A1h[(size_t)N_TOK * D_MOD];   // gathered unmasked hL rows, fp16
__device__ __half d_B1h[(size_t)KF * D_MOD];      // W1 transposed: row n=e*512+f, col k
__device__ __half d_A2h[(size_t)N_TOK * KF];      // windowed+scaled hidden, compact masked
__device__ __half d_B2h[(size_t)D_MOD * KF];      // W2 transposed: row n, col k
__device__ float d_hid[(size_t)N_TOK * KF];       // gelu(hL@W1+b1), token-indexed
__device__ float d_mixed[(size_t)N_TOK * D_MOD];  // compact masked rows
__device__ float d_w[N_TOK * N_EXP];
__device__ float d_ws[N_TOK * N_EXP];
__device__ unsigned char d_unm[N_TOK];
__device__ int d_cnt[N_TOK];
__device__ int d_mList[N_TOK];
__device__ int d_uList[N_TOK];
__device__ int d_mNum, d_uNum, d_r;

// ---------------- PTX helpers ----------------
__device__ __forceinline__ unsigned s2u(const void* p) {
    unsigned a;
    asm("{ .reg .u64 t; cvta.to.shared.u64 t, %1; cvt.u32.u64 %0, t; }" : "=r"(a) : "l"(p));
    return a;
}
__device__ __forceinline__ void cp16(unsigned d, const void* s) {
    asm volatile("cp.async.cg.shared.global [%0], [%1], 16;\n" :: "r"(d), "l"(s));
}
#define CP_COMMIT() asm volatile("cp.async.commit_group;\n")
#define CP_WAIT1()  asm volatile("cp.async.wait_group 1;\n" ::: "memory")
#define CP_WAIT0()  asm volatile("cp.async.wait_group 0;\n" ::: "memory")

#define LDSM4(r0, r1, r2, r3, addr) \
    asm volatile("ldmatrix.sync.aligned.m8n8.x4.shared.b16 {%0,%1,%2,%3}, [%4];" \
                 : "=r"(r0), "=r"(r1), "=r"(r2), "=r"(r3) : "r"(addr))

#define MMA16816(c0, c1, c2, c3, a0, a1, a2, a3, b0, b1) \
    asm volatile("mma.sync.aligned.m16n8k16.row.col.f32.f16.f16.f32 " \
                 "{%0,%1,%2,%3}, {%4,%5,%6,%7}, {%8,%9}, {%0,%1,%2,%3};" \
                 : "+f"(c0), "+f"(c1), "+f"(c2), "+f"(c3) \
                 : "r"(a0), "r"(a1), "r"(a2), "r"(a3), "r"(b0), "r"(b1))

// ---------------- K0: counters, mask-dtype detection, r ----------------
__global__ void k_prep(const unsigned int* __restrict__ masked, const int* __restrict__ rPtr)
{
    __shared__ int not01, notf;
    const int tid = threadIdx.x;
    if (tid == 0) {
        not01 = 0; notf = 0;
        d_mNum = 0; d_uNum = 0;
        int rv = 8;
        if (rPtr) {
            rv = rPtr[0];
            if (rv < 0 || rv > 100000) {
                float rf = __int_as_float(rv);
                rv = (rf > 0.0f && rf < 100000.0f) ? (int)rf : 8;
            }
            if (rv < 0) rv = 0;
            if (rv > S_LEN) rv = S_LEN;
        }
        d_r = rv;
    }
    __syncthreads();
    int b01 = 0, bf = 0;
    for (int i = tid; i < N_TOK / 4; i += blockDim.x) {
        unsigned int v = masked[i];
        if (v > 1u) b01 = 1;
        if (v != 0u && v != 0x3F800000u) bf = 1;
    }
    if (b01) atomicOr(&not01, 1);
    if (bf)  atomicOr(&notf, 1);
    __syncthreads();
    const int mode = (!not01) ? 1 : ((!notf) ? 2 : 0);
    for (int t = tid; t < N_TOK; t += blockDim.x) {
        int mk;
        if (mode == 1)      mk = ((const int*)masked)[t];
        else if (mode == 2) mk = (((const float*)masked)[t] != 0.0f);
        else                mk = ((const unsigned char*)masked)[t];
        d_unm[t] = (unsigned char)(mk ? 0 : 1);
    }
}

// ---------------- K1: routing softmax + cnt + compaction ----------------
__global__ __launch_bounds__(256) void k_route(const float* __restrict__ hL,
                                               const float* __restrict__ Wr,
                                               const float* __restrict__ br)
{
    const int t = blockIdx.x;
    const int tid = threadIdx.x;
    const float* __restrict__ h = hL + (size_t)t * D_MOD;

    float acc[8];
#pragma unroll
    for (int k = 0; k < 8; k++) acc[k] = 0.0f;
    for (int d = tid; d < D_MOD; d += 256) {
        float hv = h[d];
        const float4* wr = (const float4*)(Wr + (size_t)d * 8);
        float4 w0 = wr[0], w1 = wr[1];
        acc[0] = fmaf(hv, w0.x, acc[0]); acc[1] = fmaf(hv, w0.y, acc[1]);
        acc[2] = fmaf(hv, w0.z, acc[2]); acc[3] = fmaf(hv, w0.w, acc[3]);
        acc[4] = fmaf(hv, w1.x, acc[4]); acc[5] = fmaf(hv, w1.y, acc[5]);
        acc[6] = fmaf(hv, w1.z, acc[6]); acc[7] = fmaf(hv, w1.w, acc[7]);
    }
#pragma unroll
    for (int k = 0; k < 8; k++) {
#pragma unroll
        for (int o = 16; o; o >>= 1) acc[k] += __shfl_xor_sync(0xffffffffu, acc[k], o);
    }
    __shared__ float sl[8][8];
    if ((tid & 31) == 0) {
#pragma unroll
        for (int k = 0; k < 8; k++) sl[tid >> 5][k] = acc[k];
    }
    __syncthreads();
    if (tid == 0) {
        float lg[8];
#pragma unroll
        for (int k = 0; k < 8; k++) {
            float s = br[k];
            for (int wgi = 0; wgi < 8; wgi++) s += sl[wgi][k];
            lg[k] = s;
        }
        const int b = t / S_LEN, s0 = t - b * S_LEN;
        const int r = d_r;
        int lo = s0 - r; if (lo < 0) lo = 0;
        int hi = s0 + r; if (hi > S_LEN - 1) hi = S_LEN - 1;
        int c = 0;
        for (int j = lo; j <= hi; j++)
            if (j != s0) c += (int)d_unm[b * S_LEN + j];
        d_cnt[t] = c;

        float mx = lg[0];
#pragma unroll
        for (int k = 1; k < 8; k++) mx = fmaxf(mx, lg[k]);
        float e[8], ssum = 0.0f;
#pragma unroll
        for (int k = 0; k < 8; k++) { e[k] = expf(lg[k] - mx); ssum += e[k]; }
        const float inv = 1.0f / ssum;
        const float cinv = 1.0f / (float)(c > 0 ? c : 1);
#pragma unroll
        for (int k = 0; k < 8; k++) {
            float wv = e[k] * inv;
            d_w[t * 8 + k] = wv;
            d_ws[t * 8 + k] = wv * cinv;
        }
        if (d_unm[t]) { int u = atomicAdd(&d_uNum, 1); d_uList[u] = t; }
        else          { int mm = atomicAdd(&d_mNum, 1); d_mList[mm] = t; }
    }
}

// ---------------- K2: gather unmasked hL rows -> fp16 (A1) ----------------
__global__ __launch_bounds__(256) void k_cvtA1(const float* __restrict__ hL)
{
    const int m = blockIdx.x;
    if (m >= d_uNum) return;
    const int t = d_uList[m];
    const float4* src = (const float4*)(hL + (size_t)t * D_MOD);
    __half* dst = d_A1h + (size_t)m * D_MOD;
    for (int i = threadIdx.x; i < D_MOD / 4; i += 256) {
        float4 v = src[i];
        __half2 p0 = __floats2half2_rn(v.x, v.y);
        __half2 p1 = __floats2half2_rn(v.z, v.w);
        *(uint2*)(dst + i * 4) = make_uint2(*(unsigned*)&p0, *(unsigned*)&p1);
    }
}

// ---------------- transpose + fp16 convert: W[K,N] -> B[N,K] ----------------
__device__ __forceinline__ void tr_body(const float* __restrict__ Wp,
                                        __half* __restrict__ Bp, int Kd, int Nd)
{
    __shared__ float tl[32][33];
    const int tx = threadIdx.x & 31, ty = threadIdx.x >> 5;
    const int n0 = blockIdx.x * 32, k0 = blockIdx.y * 32;
#pragma unroll
    for (int j = 0; j < 4; j++) {
        int r = ty + j * 8;
        tl[r][tx] = Wp[(size_t)(k0 + r) * Nd + n0 + tx];
    }
    __syncthreads();
#pragma unroll
    for (int j = 0; j < 4; j++) {
        int r = ty + j * 8;
        Bp[(size_t)(n0 + r) * Kd + k0 + tx] = __float2half_rn(tl[tx][r]);
    }
}
__global__ __launch_bounds__(256) void k_tr1(const float* __restrict__ W1) {
    tr_body(W1 + (size_t)blockIdx.z * D_MOD * F_HID,
            d_B1h + (size_t)blockIdx.z * F_HID * D_MOD, D_MOD, F_HID);
}
__global__ __launch_bounds__(256) void k_tr2(const float* __restrict__ W2) {
    tr_body(W2, d_B2h, KF, D_MOD);
}

// ---------------- HMMA GEMM: 128x128 CTA tile, 8 warps, cp.async double buffer ----
// MODE 0: hid[uList[m]][n] = gelu(A1[m] . B1[n] + b1[n]),  M=uNum, N=4096, K=2048
// MODE 1: mixed[m][n]      = A2[m] . B2[n],                M=mNum, N=2048, K=4096
template <int MODE>
__global__ __launch_bounds__(256, 2) void k_mm(const float* __restrict__ bias)
{
    constexpr int KDIM = (MODE == 0) ? D_MOD : KF;
    constexpr int KT = KDIM / 32;
    const __half* __restrict__ A  = (MODE == 0) ? d_A1h : d_A2h;
    const __half* __restrict__ Bm = (MODE == 0) ? d_B1h : d_B2h;
    const int M = (MODE == 0) ? d_uNum : d_mNum;
    const int m0 = blockIdx.y * 128;
    if (m0 >= M) return;
    const int n0 = blockIdx.x * 128;

    // padded stride 40 halves (80B): conflict-free ldmatrix, 16B-aligned segments
    __shared__ __align__(16) __half sA[2][128 * 40];
    __shared__ __align__(16) __half sB[2][128 * 40];

    const int tid = threadIdx.x;
    const int wid = tid >> 5, l = tid & 31;
    const unsigned baseA = s2u(&sA[0][0]);
    const unsigned baseB = s2u(&sB[0][0]);

    auto load_tile = [&](int buf, int kt) {
#pragma unroll
        for (int h = 0; h < 2; h++) {
            const int c = tid + h * 256;          // 512 16B chunks per tile
            const int r = c >> 2, sg = c & 3;
            const unsigned off = (unsigned)(buf * 5120 + r * 40 + sg * 8) * 2u;
            cp16(baseA + off, A + (size_t)(m0 + r) * KDIM + kt * 32 + sg * 8);
            cp16(baseB + off, Bm + (size_t)(n0 + r) * KDIM + kt * 32 + sg * 8);
        }
        CP_COMMIT();
    };

    load_tile(0, 0);
    load_tile(1, 1);

    float acc[4][4][4];
#pragma unroll
    for (int i = 0; i < 4; i++)
#pragma unroll
        for (int j = 0; j < 4; j++)
#pragma unroll
            for (int q = 0; q < 4; q++) acc[i][j][q] = 0.0f;

    const int wm = (wid >> 2) * 64, wn = (wid & 3) * 32;
    const int aRow = l & 15;
    const int aCol = (l >> 4) * 8;
    const int bRow = (l & 7) + ((l >> 4) & 1) * 8;
    const int bCol = ((l >> 3) & 1) * 8;

    for (int kt = 0; kt < KT; kt++) {
        if (kt < KT - 1) { CP_WAIT1(); } else { CP_WAIT0(); }
        __syncthreads();
        const int buf = kt & 1;
        const unsigned abuf = baseA + buf * 10240u;
        const unsigned bbuf = baseB + buf * 10240u;
#pragma unroll
        for (int ks = 0; ks < 2; ks++) {
            const int k0 = ks * 16;
            unsigned ar[4][4], br[2][4];
#pragma unroll
            for (int mi = 0; mi < 4; mi++) {
                unsigned ad = abuf + (unsigned)((wm + mi * 16 + aRow) * 40 + k0 + aCol) * 2u;
                LDSM4(ar[mi][0], ar[mi][1], ar[mi][2], ar[mi][3], ad);
            }
#pragma unroll
            for (int nj = 0; nj < 2; nj++) {
                unsigned bd = bbuf + (unsigned)((wn + nj * 16 + bRow) * 40 + k0 + bCol) * 2u;
                LDSM4(br[nj][0], br[nj][1], br[nj][2], br[nj][3], bd);
            }
#pragma unroll
            for (int mi = 0; mi < 4; mi++)
#pragma unroll
                for (int ni = 0; ni < 4; ni++)
                    MMA16816(acc[mi][ni][0], acc[mi][ni][1], acc[mi][ni][2], acc[mi][ni][3],
                             ar[mi][0], ar[mi][1], ar[mi][2], ar[mi][3],
                             br[ni >> 1][(ni & 1) * 2], br[ni >> 1][(ni & 1) * 2 + 1]);
        }
        __syncthreads();
        if (kt + 2 < KT) load_tile(buf, kt + 2);
    }

    // ---- epilogue ----
#pragma unroll
    for (int mi = 0; mi < 4; mi++) {
#pragma unroll
        for (int hh = 0; hh < 2; hh++) {
            const int m = m0 + wm + mi * 16 + (l >> 2) + hh * 8;
            if (m >= M) continue;
            int t = 0;
            if (MODE == 0) t = d_uList[m];
#pragma unroll
            for (int ni = 0; ni < 4; ni++) {
                const int n = n0 + wn + ni * 8 + (l & 3) * 2;
                float v0 = acc[mi][ni][hh * 2 + 0];
                float v1 = acc[mi][ni][hh * 2 + 1];
                if (MODE == 0) {
                    float x0 = v0 + bias[n];
                    float x1 = v1 + bias[n + 1];
                    float2 o;
                    o.x = 0.5f * x0 * (1.0f + erff(x0 * 0.70710678118654752f));
                    o.y = 0.5f * x1 * (1.0f + erff(x1 * 0.70710678118654752f));
                    *(float2*)(d_hid + (size_t)t * KF + n) = o;
                } else {
                    *(float2*)(d_mixed + (size_t)m * D_MOD + n) = make_float2(v0, v1);
                }
            }
        }
    }
}

// ---------------- K3: windowed gather + (w/cnt) scaling -> fp16 (A2, compact) ----
__global__ __launch_bounds__(512) void k_window()
{
    const int m = blockIdx.x;
    if (m >= d_mNum) return;
    const int t = d_mList[m];
    const int b = t / S_LEN, s = t - b * S_LEN;
    const int r = d_r;
    int lo = s - r; if (lo < 0) lo = 0;
    int hi = s + r; if (hi > S_LEN - 1) hi = S_LEN - 1;
    const int tid = threadIdx.x;

    float4 a0 = make_float4(0.f, 0.f, 0.f, 0.f);
    float4 a1 = make_float4(0.f, 0.f, 0.f, 0.f);
    for (int j = lo; j <= hi; j++) {
        if (!d_unm[b * S_LEN + j]) continue;
        const float4* h = (const float4*)(d_hid + (size_t)(b * S_LEN + j) * KF);
        float4 v0 = h[tid], v1 = h[tid + 512];
        a0.x += v0.x; a0.y += v0.y; a0.z += v0.z; a0.w += v0.w;
        a1.x += v1.x; a1.y += v1.y; a1.z += v1.z; a1.w += v1.w;
    }
    const float s0 = d_ws[t * N_EXP + (tid >> 7)];
    const float s1 = d_ws[t * N_EXP + (tid >> 7) + 4];

    __half* row = d_A2h + (size_t)m * KF;
    __half2 p0 = __floats2half2_rn(a0.x * s0, a0.y * s0);
    __half2 p1 = __floats2half2_rn(a0.z * s0, a0.w * s0);
    *(uint2*)(row + tid * 4) = make_uint2(*(unsigned*)&p0, *(unsigned*)&p1);
    __half2 q0 = __floats2half2_rn(a1.x * s1, a1.y * s1);
    __half2 q1 = __floats2half2_rn(a1.z * s1, a1.w * s1);
    *(uint2*)(row + 2048 + tid * 4) = make_uint2(*(unsigned*)&q0, *(unsigned*)&q1);
}

// ---------------- K5: bias (Σ w_k b2_k) + LayerNorm + scatter ----------------
__global__ __launch_bounds__(256) void k_final(const float* __restrict__ b2,
                                               float* __restrict__ out)
{
    const int m = blockIdx.x;
    if (m >= d_mNum) return;
    const int t = d_mList[m];
    if (d_cnt[t] <= 0) return;
    const int tid = threadIdx.x;

    float w[8];
#pragma unroll
    for (int k = 0; k < 8; k++) w[k] = d_w[t * 8 + k];

    float x[8];
    float sum = 0.0f;
#pragma unroll
    for (int i = 0; i < 8; i++) {
        const int d = tid + (i << 8);
        float v = d_mixed[(size_t)m * D_MOD + d];
        float bias = 0.0f;
#pragma unroll
        for (int k = 0; k < 8; k++) bias = fmaf(w[k], b2[k * D_MOD + d], bias);
        v += bias;
        x[i] = v;
        sum += v;
    }
    __shared__ float sh[8];
#pragma unroll
    for (int o = 16; o; o >>= 1) sum += __shfl_xor_sync(0xffffffffu, sum, o);
    if ((tid & 31) == 0) sh[tid >> 5] = sum;
    __syncthreads();
    const float mu = (sh[0] + sh[1] + sh[2] + sh[3] + sh[4] + sh[5] + sh[6] + sh[7]) *
                     (1.0f / (float)D_MOD);
    __syncthreads();
    float vs = 0.0f;
#pragma unroll
    for (int i = 0; i < 8; i++) { float dd = x[i] - mu; vs = fmaf(dd, dd, vs); }
#pragma unroll
    for (int o = 16; o; o >>= 1) vs += __shfl_xor_sync(0xffffffffu, vs, o);
    if ((tid & 31) == 0) sh[tid >> 5] = vs;
    __syncthreads();
    const float var = (sh[0] + sh[1] + sh[2] + sh[3] + sh[4] + sh[5] + sh[6] + sh[7]) *
                      (1.0f / (float)D_MOD);
    const float rstd = rsqrtf(var + 1e-5f);
    float* op = out + (size_t)t * D_MOD;
#pragma unroll
    for (int i = 0; i < 8; i++) op[tid + (i << 8)] = (x[i] - mu) * rstd;
}

// ---------------- launch ----------------
extern "C" void kernel_launch(void* const* d_in, const int* in_sizes, int n_in,
                              void* d_out, int out_size)
{
    const float* hL = (const float*)d_in[0];
    const void*  mk = d_in[1];
    const float* Wr = (const float*)d_in[2];
    const float* br = (const float*)d_in[3];
    const float* W1 = (const float*)d_in[4];
    const float* b1 = (const float*)d_in[5];
    const float* W2 = (const float*)d_in[6];
    const float* b2 = (const float*)d_in[7];
    const int*   rp = (n_in > 8) ? (const int*)d_in[8] : nullptr;
    float* out = (float*)d_out;

    cudaMemsetAsync(out, 0, (size_t)out_size * sizeof(float));

    k_prep<<<1, 256>>>((const unsigned int*)mk, rp);
    k_route<<<N_TOK, 256>>>(hL, Wr, br);
    k_cvtA1<<<N_TOK, 256>>>(hL);                      // guards on d_uNum
    k_tr1<<<dim3(F_HID / 32, D_MOD / 32, N_EXP), 256>>>(W1);
    k_mm<0><<<dim3(32, 32), 256>>>(b1);               // worst-case grid; guards on d_uNum
    k_window<<<N_TOK, 512>>>();                       // guards on d_mNum
    k_tr2<<<dim3(D_MOD / 32, KF / 32), 256>>>(W2);
    k_mm<1><<<dim3(16, 32), 256>>>(nullptr);          // worst-case grid; guards on d_mNum
    k_final<<<N_TOK, 256>>>(b2, out);
    (void)in_sizes;
}